// round 6
// baseline (speedup 1.0000x reference)
#include <cuda_runtime.h>
#include <cuda_bf16.h>
#include <cstdint>

// ==========================================================================
// Pre-split bf16 hi/lo weights, row-major [K][256] per plane.
// w1 stage bases {0, 131072, 393216}, lo plane at +K*256.
// w2 stage s: 917504 + s*131072, lo at +65536. Total 1310720 bf16 = 2.5MB.
// ==========================================================================
__device__ __align__(16) __nv_bfloat16 g_wscr[1310720];

// ---------------- PTX helpers (all baseline sm_80+ PTX) ----------------
__device__ __forceinline__ uint32_t s2u(const void* p) {
    return (uint32_t)__cvta_generic_to_shared(p);
}
__device__ __forceinline__ void ldsm4(uint32_t* r, uint32_t a) {
    asm volatile("ldmatrix.sync.aligned.m8n8.x4.shared.b16 {%0,%1,%2,%3}, [%4];"
                 : "=r"(r[0]), "=r"(r[1]), "=r"(r[2]), "=r"(r[3]) : "r"(a));
}
__device__ __forceinline__ void ldsm4t(uint32_t* r, uint32_t a) {
    asm volatile("ldmatrix.sync.aligned.m8n8.x4.trans.shared.b16 {%0,%1,%2,%3}, [%4];"
                 : "=r"(r[0]), "=r"(r[1]), "=r"(r[2]), "=r"(r[3]) : "r"(a));
}
__device__ __forceinline__ void mma_bf16(float* d, const uint32_t* a,
                                         uint32_t b0, uint32_t b1) {
    asm volatile(
        "mma.sync.aligned.m16n8k16.row.col.f32.bf16.bf16.f32 "
        "{%0,%1,%2,%3}, {%4,%5,%6,%7}, {%8,%9}, {%0,%1,%2,%3};"
        : "+f"(d[0]), "+f"(d[1]), "+f"(d[2]), "+f"(d[3])
        : "r"(a[0]), "r"(a[1]), "r"(a[2]), "r"(a[3]), "r"(b0), "r"(b1));
}
__device__ __forceinline__ void cpa16(uint32_t dst, const void* src) {
    asm volatile("cp.async.cg.shared.global [%0], [%1], 16;" :: "r"(dst), "l"(src));
}
#define CPA_COMMIT() asm volatile("cp.async.commit_group;" ::: "memory")
#define CPA_WAIT1()  asm volatile("cp.async.wait_group 1;" ::: "memory")
#define CPA_WAIT0()  asm volatile("cp.async.wait_group 0;" ::: "memory")

// ==========================================================================
// Prep: fp32 weights -> bf16 hi/lo planes, row-major.
// ==========================================================================
struct PrepP { const float* w1[3]; const float* w2[3]; };

__global__ void prep_weights(PrepP pp) {
    for (int idx = blockIdx.x * blockDim.x + threadIdx.x; idx < 655360;
         idx += gridDim.x * blockDim.x) {
        int s, j;
        const float* src;
        long long hioff, looff;
        if (idx < 458752) {
            if (idx < 65536)       { s = 0; j = idx;          hioff = 0;      looff = 65536; }
            else if (idx < 196608) { s = 1; j = idx - 65536;  hioff = 131072; looff = 131072 + 131072; }
            else                   { s = 2; j = idx - 196608; hioff = 393216; looff = 393216 + 262144; }
            src = pp.w1[s];
        } else {
            int i = idx - 458752;
            s = i >> 16; j = i & 65535;
            src = pp.w2[s];
            hioff = 917504LL + s * 131072;
            looff = hioff + 65536;
        }
        float v = src[j];
        __nv_bfloat16 hi = __float2bfloat16(v);
        __nv_bfloat16 lo = __float2bfloat16(v - __bfloat162float(hi));
        g_wscr[hioff + j] = hi;
        g_wscr[looff + j] = lo;
    }
}

// ==========================================================================
// Main fused kernel. MT=32 rows/block, KC=32, 512 thr = 16 warps (2M x 8N).
// ==========================================================================
struct MP {
    const float* feat[3];
    const void*  pid[3];
    const float* b1[3];
    const float* b2[3];
    float* out;
    int C[3];
    int HW[3];
};

// smem (A rows 80B padded; B/hidden rows 528B padded)
constexpr int ABUF    = 5120;         // hi(2560)+lo(2560) per buffer
constexpr int OFF_A   = 0;            // 2 buffers
constexpr int OFF_B   = 10240;        // 2 bufs x (hi+lo) x 32 x 528
constexpr int BPLANE  = 16896;
constexpr int BBUF    = 33792;
constexpr int OFF_H   = 77824;        // hidden hi/lo planes
constexpr int HPLANE  = 16896;
constexpr int OFF_PN  = 111616;       // float pn[8][32]
constexpr int OFF_FLAG = 112640;
constexpr int SMEM_ALLOC = 112656;

// One K16 step: warp covers 32 cols (4 n8 frags), 3-term bf16 split.
__device__ __forceinline__ void mma_step(float acc[4][4], uint32_t aHi,
                                         uint32_t aLo, uint32_t bRow, int wn) {
    uint32_t ah[4], al[4];
    ldsm4(ah, aHi);
    ldsm4(al, aLo);
#pragma unroll
    for (int nf = 0; nf < 2; nf++) {
        uint32_t bh[4], bl[4];
        uint32_t bc = bRow + (uint32_t)(wn * 64 + nf * 32);
        ldsm4t(bh, bc);
        ldsm4t(bl, bc + BPLANE);
        mma_bf16(acc[nf * 2], ah, bh[0], bh[1]);
        mma_bf16(acc[nf * 2], ah, bl[0], bl[1]);
        mma_bf16(acc[nf * 2], al, bh[0], bh[1]);
        mma_bf16(acc[nf * 2 + 1], ah, bh[2], bh[3]);
        mma_bf16(acc[nf * 2 + 1], ah, bl[2], bl[3]);
        mma_bf16(acc[nf * 2 + 1], al, bh[2], bh[3]);
    }
}

__global__ __launch_bounds__(512, 2) void patch_mlp_mma(MP p) {
    extern __shared__ char sm[];
    const int tid  = threadIdx.x;
    const int lane = tid & 31;
    const int wid  = tid >> 5;
    const int wm   = wid & 1;        // M group (16 rows)
    const int wn   = wid >> 1;       // N group (32 cols), 0..7
    const int ti   = lane & 3;
    const int g    = lane >> 2;

    const int s    = blockIdx.x % 3;
    const int tile = blockIdx.x / 3;
    const int m0   = tile * 32;
    const int C    = p.C[s];
    const long long HW = p.HW[s];
    const float* __restrict__ feat = p.feat[s];

    int* flag = (int*)(sm + OFF_FLAG);
    if (tid == 0) *flag = 1;
    __syncthreads();
    if (tid < 128) {
        long long v = ((const long long*)p.pid[s])[tid];
        if (v < 0 || v >= HW) *flag = 0;
    }
    __syncthreads();
    const int is64 = *flag;

    // gather mapping: row = tid&31, kslot = tid>>5 (0..15): loads k, k+16
    const int grow  = tid & 31;
    const int kslot = tid >> 5;
    long long rbase;
    {
        int m = m0 + grow, b = m >> 8, pi = m & 255;
        long long sp = is64 ? ((const long long*)p.pid[s])[pi]
                            : (long long)((const int*)p.pid[s])[pi];
        rbase = (long long)b * C * HW + sp;
    }
    const float* gp = feat + rbase + (long long)kslot * HW;
    const long long j16 = 16 * HW, kb = 32 * HW;

    float acc[4][4];
#pragma unroll
    for (int i = 0; i < 4; i++)
#pragma unroll
        for (int jj = 0; jj < 4; jj++) acc[i][jj] = 0.f;

    const int nch = C >> 5;
    const long long w1base = (s == 0) ? 0LL : (s == 1) ? 131072LL : 393216LL;
    const long long Koff   = (long long)C << 8;

    const uint32_t smb  = s2u(sm);
    const uint32_t aFr  = smb + OFF_A + (wm * 16 + (lane & 15)) * 80 + (lane >> 4) * 16;
    const uint32_t bFr  = smb + OFF_B + (lane & 15) * 528 + (lane >> 4) * 16;

    // ---------------- GEMM1 ----------------
    float gv0 = __ldg(gp), gv1 = __ldg(gp + j16);
    {   // B chunk 0 -> buf0
        const __nv_bfloat16* w = g_wscr + w1base;
        uint32_t dst = smb + OFF_B;
#pragma unroll
        for (int i = tid; i < 2048; i += 512) {
            int pl = i >> 10, k = (i >> 5) & 31, cc = i & 31;
            cpa16(dst + pl * BPLANE + k * 528 + cc * 16, w + pl * Koff + k * 256 + cc * 8);
        }
    }
    CPA_COMMIT();

    for (int c = 0; c < nch; c++) {
        // 1. convert current gather regs -> A[c&1]
        {
            char* ab = sm + OFF_A + (c & 1) * ABUF;
            __nv_bfloat16 h0 = __float2bfloat16(gv0);
            __nv_bfloat16 h1 = __float2bfloat16(gv1);
            int o = grow * 80 + kslot * 2;
            *(__nv_bfloat16*)(ab + o)             = h0;
            *(__nv_bfloat16*)(ab + o + 32)        = h1;
            *(__nv_bfloat16*)(ab + 2560 + o)      = __float2bfloat16(gv0 - __bfloat162float(h0));
            *(__nv_bfloat16*)(ab + 2560 + o + 32) = __float2bfloat16(gv1 - __bfloat162float(h1));
        }
        // 2. barrier: chunk c-1 MMAs done everywhere; A[c&1]/B visible after
        __syncthreads();
        // 3. prefetch gather chunk c+1
        if (c + 1 < nch) {
            const float* gpc = gp + (long long)(c + 1) * kb;
            gv0 = __ldg(gpc);
            gv1 = __ldg(gpc + j16);
        }
        // 4. stream B chunk c+1 (safe: everyone passed barrier => done with buf)
        if (c + 1 < nch) {
            const __nv_bfloat16* w = g_wscr + w1base + (long long)(c + 1) * 8192;
            uint32_t dst = smb + OFF_B + ((c + 1) & 1) * BBUF;
#pragma unroll
            for (int i = tid; i < 2048; i += 512) {
                int pl = i >> 10, k = (i >> 5) & 31, cc = i & 31;
                cpa16(dst + pl * BPLANE + k * 528 + cc * 16, w + pl * Koff + k * 256 + cc * 8);
            }
            CPA_COMMIT();
            CPA_WAIT1();
        } else {
            CPA_WAIT0();
        }
        __syncwarp();
        // 5. MMA chunk c
        uint32_t aHi = aFr + (c & 1) * ABUF;
        uint32_t bb  = bFr + (c & 1) * BBUF;
#pragma unroll
        for (int kk = 0; kk < 2; kk++)
            mma_step(acc, aHi + kk * 32, aHi + 2560 + kk * 32, bb + kk * 16 * 528, wn);
    }

    // ---- stream GEMM2 B chunk0 (buf0; safe: nch even, last chunk used buf1,
    //      and the last barrier guaranteed buf0's readers (chunk nch-2) done) ----
    const long long w2base = 917504LL + (long long)s * 131072;
    {
        const __nv_bfloat16* w = g_wscr + w2base;
        uint32_t dst = smb + OFF_B;
#pragma unroll
        for (int i = tid; i < 2048; i += 512) {
            int pl = i >> 10, k = (i >> 5) & 31, cc = i & 31;
            cpa16(dst + pl * BPLANE + k * 528 + cc * 16, w + pl * 65536 + k * 256 + cc * 8);
        }
    }
    CPA_COMMIT();

    // ---------------- epilogue 1: relu + bias -> hidden hi/lo ----------------
    {
        const float* __restrict__ b1 = p.b1[s];
        const int r0 = wm * 16 + g;
#pragma unroll
        for (int nf = 0; nf < 4; nf++) {
            int c0 = wn * 32 + nf * 8 + ti * 2;
            float ba = __ldg(b1 + c0), bbv = __ldg(b1 + c0 + 1);
            float v0 = fmaxf(acc[nf][0] + ba, 0.f);
            float v1 = fmaxf(acc[nf][1] + bbv, 0.f);
            float v2 = fmaxf(acc[nf][2] + ba, 0.f);
            float v3 = fmaxf(acc[nf][3] + bbv, 0.f);
            __nv_bfloat16 h0 = __float2bfloat16(v0), h1 = __float2bfloat16(v1);
            __nv_bfloat16 h2 = __float2bfloat16(v2), h3 = __float2bfloat16(v3);
            __nv_bfloat162 hi01; hi01.x = h0; hi01.y = h1;
            __nv_bfloat162 hi23; hi23.x = h2; hi23.y = h3;
            __nv_bfloat162 lo01, lo23;
            lo01.x = __float2bfloat16(v0 - __bfloat162float(h0));
            lo01.y = __float2bfloat16(v1 - __bfloat162float(h1));
            lo23.x = __float2bfloat16(v2 - __bfloat162float(h2));
            lo23.y = __float2bfloat16(v3 - __bfloat162float(h3));
            *(__nv_bfloat162*)(sm + OFF_H + r0 * 528 + c0 * 2)                = hi01;
            *(__nv_bfloat162*)(sm + OFF_H + (r0 + 8) * 528 + c0 * 2)          = hi23;
            *(__nv_bfloat162*)(sm + OFF_H + HPLANE + r0 * 528 + c0 * 2)       = lo01;
            *(__nv_bfloat162*)(sm + OFF_H + HPLANE + (r0 + 8) * 528 + c0 * 2) = lo23;
#pragma unroll
            for (int jj = 0; jj < 4; jj++) acc[nf][jj] = 0.f;
        }
    }

    // ---------------- GEMM2: K=256, 8 chunks ----------------
    const uint32_t aRow2 = smb + OFF_H + (wm * 16 + (lane & 15)) * 528 + (lane >> 4) * 16;
    for (int c2 = 0; c2 < 8; c2++) {
        __syncthreads();   // c2=0: hidden visible; c2>0: B buf reuse safe
        if (c2 + 1 < 8) {
            const __nv_bfloat16* w = g_wscr + w2base + (long long)(c2 + 1) * 8192;
            uint32_t dst = smb + OFF_B + ((c2 + 1) & 1) * BBUF;
#pragma unroll
            for (int i = tid; i < 2048; i += 512) {
                int pl = i >> 10, k = (i >> 5) & 31, cc = i & 31;
                cpa16(dst + pl * BPLANE + k * 528 + cc * 16, w + pl * 65536 + k * 256 + cc * 8);
            }
            CPA_COMMIT();
            CPA_WAIT1();
        } else {
            CPA_WAIT0();
        }
        __syncwarp();
        uint32_t bb = bFr + (c2 & 1) * BBUF;
#pragma unroll
        for (int kk = 0; kk < 2; kk++)
            mma_step(acc, aRow2 + c2 * 64 + kk * 32,
                     aRow2 + HPLANE + c2 * 64 + kk * 32, bb + kk * 16 * 528, wn);
    }

    // ---------------- epilogue 2: bias, L2 norm, store ----------------
    {
        const float* __restrict__ b2 = p.b2[s];
        float b2a[4], b2b[4];
#pragma unroll
        for (int nf = 0; nf < 4; nf++) {
            int c0 = wn * 32 + nf * 8 + ti * 2;
            b2a[nf] = __ldg(b2 + c0);
            b2b[nf] = __ldg(b2 + c0 + 1);
        }
        float s0 = 0.f, s1 = 0.f;
#pragma unroll
        for (int nf = 0; nf < 4; nf++) {
            float v0 = acc[nf][0] + b2a[nf], v1 = acc[nf][1] + b2b[nf];
            float v2 = acc[nf][2] + b2a[nf], v3 = acc[nf][3] + b2b[nf];
            s0 += v0 * v0 + v1 * v1;
            s1 += v2 * v2 + v3 * v3;
        }
        s0 += __shfl_xor_sync(0xffffffffu, s0, 1);
        s0 += __shfl_xor_sync(0xffffffffu, s0, 2);
        s1 += __shfl_xor_sync(0xffffffffu, s1, 1);
        s1 += __shfl_xor_sync(0xffffffffu, s1, 2);
        float* pn = (float*)(sm + OFF_PN);
        const int r0 = wm * 16 + g;
        __syncthreads();
        if (ti == 0) {
            pn[wn * 32 + r0]     = s0;
            pn[wn * 32 + r0 + 8] = s1;
        }
        __syncthreads();
        float t0 = 0.f, t1 = 0.f;
#pragma unroll
        for (int w = 0; w < 8; w++) {
            t0 += pn[w * 32 + r0];
            t1 += pn[w * 32 + r0 + 8];
        }
        float sc0 = 1.f / (sqrtf(t0) + 1e-7f);
        float sc1 = 1.f / (sqrtf(t1) + 1e-7f);
        float* o0 = p.out + ((long long)s * 4096 + m0 + r0) * 256;
        float* o1 = o0 + 8 * 256;
#pragma unroll
        for (int nf = 0; nf < 4; nf++) {
            int c0 = wn * 32 + nf * 8 + ti * 2;
            float2 u0, u1;
            u0.x = (acc[nf][0] + b2a[nf]) * sc0;
            u0.y = (acc[nf][1] + b2b[nf]) * sc0;
            u1.x = (acc[nf][2] + b2a[nf]) * sc1;
            u1.y = (acc[nf][3] + b2b[nf]) * sc1;
            *(float2*)(o0 + c0) = u0;
            *(float2*)(o1 + c0) = u1;
        }
    }
}

// ==========================================================================
extern "C" void kernel_launch(void* const* d_in, const int* in_sizes, int n_in,
                              void* d_out, int out_size) {
    (void)n_in; (void)out_size;
    int fi[3], pi[3], w1i[3], b1i[3], w2i[3], b2i[3];
    if (in_sizes[1] == 256) {
        for (int s = 0; s < 3; s++) {  // dict order: feat,pid,w1,b1,w2,b2 per stage
            int b = 6 * s;
            fi[s] = b; pi[s] = b + 1; w1i[s] = b + 2;
            b1i[s] = b + 3; w2i[s] = b + 4; b2i[s] = b + 5;
        }
    } else {
        for (int s = 0; s < 3; s++) {  // signature order
            fi[s] = s; pi[s] = 3 + s;
            int b = 6 + 4 * s;
            w1i[s] = b; b1i[s] = b + 1; w2i[s] = b + 2; b2i[s] = b + 3;
        }
    }

    PrepP pw;
    MP p;
    for (int s = 0; s < 3; s++) {
        p.feat[s] = (const float*)d_in[fi[s]];
        p.pid[s]  = (const void*)d_in[pi[s]];
        pw.w1[s]  = (const float*)d_in[w1i[s]];
        p.b1[s]   = (const float*)d_in[b1i[s]];
        pw.w2[s]  = (const float*)d_in[w2i[s]];
        p.b2[s]   = (const float*)d_in[b2i[s]];
        p.C[s]    = in_sizes[w1i[s]] / 256;
        p.HW[s]   = in_sizes[fi[s]] / (16 * p.C[s]);
    }
    p.out = (float*)d_out;

    static bool attr_set = false;
    if (!attr_set) {
        cudaFuncSetAttribute(patch_mlp_mma,
                             cudaFuncAttributeMaxDynamicSharedMemorySize,
                             SMEM_ALLOC);
        attr_set = true;
    }

    prep_weights<<<640, 256>>>(pw);
    patch_mlp_mma<<<384, 512, SMEM_ALLOC>>>(p);
}

// round 8
// speedup vs baseline: 1.3110x; 1.3110x over previous
#include <cuda_runtime.h>
#include <cuda_bf16.h>
#include <cstdint>

// ==========================================================================
// Pre-split bf16 hi/lo weights, row-major [K][256] per plane.
// w1 stage bases {0, 131072, 393216}, lo plane at +K*256.
// w2 stage s: 917504 + s*131072, lo at +65536. Total 1310720 bf16 = 2.5MB.
// ==========================================================================
__device__ __align__(16) __nv_bfloat16 g_wscr[1310720];

// ---------------- PTX helpers (all baseline sm_80+ PTX) ----------------
__device__ __forceinline__ uint32_t s2u(const void* p) {
    return (uint32_t)__cvta_generic_to_shared(p);
}
__device__ __forceinline__ void ldsm4(uint32_t* r, uint32_t a) {
    asm volatile("ldmatrix.sync.aligned.m8n8.x4.shared.b16 {%0,%1,%2,%3}, [%4];"
                 : "=r"(r[0]), "=r"(r[1]), "=r"(r[2]), "=r"(r[3]) : "r"(a));
}
__device__ __forceinline__ void ldsm4t(uint32_t* r, uint32_t a) {
    asm volatile("ldmatrix.sync.aligned.m8n8.x4.trans.shared.b16 {%0,%1,%2,%3}, [%4];"
                 : "=r"(r[0]), "=r"(r[1]), "=r"(r[2]), "=r"(r[3]) : "r"(a));
}
__device__ __forceinline__ void mma_bf16(float* d, const uint32_t* a,
                                         uint32_t b0, uint32_t b1) {
    asm volatile(
        "mma.sync.aligned.m16n8k16.row.col.f32.bf16.bf16.f32 "
        "{%0,%1,%2,%3}, {%4,%5,%6,%7}, {%8,%9}, {%0,%1,%2,%3};"
        : "+f"(d[0]), "+f"(d[1]), "+f"(d[2]), "+f"(d[3])
        : "r"(a[0]), "r"(a[1]), "r"(a[2]), "r"(a[3]), "r"(b0), "r"(b1));
}
__device__ __forceinline__ void cpa16(uint32_t dst, const void* src) {
    asm volatile("cp.async.cg.shared.global [%0], [%1], 16;" :: "r"(dst), "l"(src));
}
#define CPA_COMMIT() asm volatile("cp.async.commit_group;" ::: "memory")
#define CPA_WAIT1()  asm volatile("cp.async.wait_group 1;" ::: "memory")
#define CPA_WAIT0()  asm volatile("cp.async.wait_group 0;" ::: "memory")

// ==========================================================================
// Prep: fp32 weights -> bf16 hi/lo planes, row-major.
// ==========================================================================
struct PrepP { const float* w1[3]; const float* w2[3]; };

__global__ void prep_weights(PrepP pp) {
    for (int idx = blockIdx.x * blockDim.x + threadIdx.x; idx < 655360;
         idx += gridDim.x * blockDim.x) {
        int s, j;
        const float* src;
        long long hioff, looff;
        if (idx < 458752) {
            if (idx < 65536)       { s = 0; j = idx;          hioff = 0;      looff = 65536; }
            else if (idx < 196608) { s = 1; j = idx - 65536;  hioff = 131072; looff = 131072 + 131072; }
            else                   { s = 2; j = idx - 196608; hioff = 393216; looff = 393216 + 262144; }
            src = pp.w1[s];
        } else {
            int i = idx - 458752;
            s = i >> 16; j = i & 65535;
            src = pp.w2[s];
            hioff = 917504LL + s * 131072;
            looff = hioff + 65536;
        }
        float v = src[j];
        __nv_bfloat16 hi = __float2bfloat16(v);
        __nv_bfloat16 lo = __float2bfloat16(v - __bfloat162float(hi));
        g_wscr[hioff + j] = hi;
        g_wscr[looff + j] = lo;
    }
}

// ==========================================================================
// Main fused kernel. MT=32 rows/block, KC=32, 256 thr = 8 warps (2M x 4N).
// ==========================================================================
struct MP {
    const float* feat[3];
    const void*  pid[3];
    const float* b1[3];
    const float* b2[3];
    float* out;
    int C[3];
    int HW[3];
};

// smem (A rows 80B padded; B/hidden rows 528B padded)
constexpr int ABUF    = 5120;         // hi(2560)+lo(2560) per buffer
constexpr int OFF_A   = 0;            // 2 buffers
constexpr int OFF_B   = 10240;        // 2 bufs x (hi+lo) x 32 x 528
constexpr int BPLANE  = 16896;
constexpr int BBUF    = 33792;
constexpr int OFF_H   = 77824;        // hidden hi/lo planes
constexpr int HPLANE  = 16896;
constexpr int OFF_PN  = 111616;       // float pn[4][32]
constexpr int OFF_FLAG = 112128;
constexpr int SMEM_ALLOC = 112144;

// One K16 x 128-col step for this warp (both A splits vs hi/lo B).
__device__ __forceinline__ void mma_step(float acc[8][4], uint32_t aHi,
                                         uint32_t aLo, uint32_t bRow, int wn) {
    uint32_t ah[4], al[4];
    ldsm4(ah, aHi);
    ldsm4(al, aLo);
#pragma unroll
    for (int pr = 0; pr < 4; pr++) {
        uint32_t bh[4], bl[4];
        uint32_t bc = bRow + (uint32_t)(wn * 64 + pr * 16) * 2;
        ldsm4t(bh, bc);
        ldsm4t(bl, bc + BPLANE);
        mma_bf16(acc[pr * 2], ah, bh[0], bh[1]);
        mma_bf16(acc[pr * 2], ah, bl[0], bl[1]);
        mma_bf16(acc[pr * 2], al, bh[0], bh[1]);
        mma_bf16(acc[pr * 2 + 1], ah, bh[2], bh[3]);
        mma_bf16(acc[pr * 2 + 1], ah, bl[2], bl[3]);
        mma_bf16(acc[pr * 2 + 1], al, bh[2], bh[3]);
    }
}

__global__ __launch_bounds__(256, 2) void patch_mlp_mma(MP p) {
    extern __shared__ char sm[];
    const int tid  = threadIdx.x;
    const int lane = tid & 31;
    const int wid  = tid >> 5;
    const int wm   = wid & 1;        // M group (16 rows)
    const int wn   = wid >> 1;       // N group (64 cols), 0..3
    const int ti   = lane & 3;
    const int g    = lane >> 2;

    const int s    = blockIdx.x % 3;
    const int tile = blockIdx.x / 3;
    const int m0   = tile * 32;
    const int C    = p.C[s];
    const long long HW = p.HW[s];
    const float* __restrict__ feat = p.feat[s];

    int* flag = (int*)(sm + OFF_FLAG);
    if (tid == 0) *flag = 1;
    __syncthreads();
    if (tid < 128) {
        long long v = ((const long long*)p.pid[s])[tid];
        if (v < 0 || v >= HW) *flag = 0;
    }
    __syncthreads();
    const int is64 = *flag;

    // gather mapping: row = tid&31, ks = tid>>5 (0..7): loads k = ks+8j
    const int grow = tid & 31;
    const int ks   = tid >> 5;
    long long rbase;
    {
        int m = m0 + grow, b = m >> 8, pi = m & 255;
        long long sp = is64 ? ((const long long*)p.pid[s])[pi]
                            : (long long)((const int*)p.pid[s])[pi];
        rbase = (long long)b * C * HW + sp;
    }
    const float* gp = feat + rbase + (long long)ks * HW;
    const long long j8 = 8 * HW, kb = 32 * HW;

    float acc[8][4];
#pragma unroll
    for (int i = 0; i < 8; i++)
#pragma unroll
        for (int jj = 0; jj < 4; jj++) acc[i][jj] = 0.f;

    const int nch = C >> 5;
    const long long w1base = (s == 0) ? 0LL : (s == 1) ? 131072LL : 393216LL;
    const long long Koff   = (long long)C << 8;

    const uint32_t smb = s2u(sm);
    const uint32_t aFr = smb + OFF_A + (wm * 16 + (lane & 15)) * 80 + (lane >> 4) * 16;
    const uint32_t bFr = smb + OFF_B + (lane & 15) * 528 + (lane >> 4) * 16;

    // ---------------- GEMM1 ----------------
    // gather prefetch depth 2: gv[parity of chunk]
    float gv[2][4];
#pragma unroll
    for (int j = 0; j < 4; j++) gv[0][j] = __ldg(gp + j * j8);
    if (nch > 1) {
        const float* gpc = gp + kb;
#pragma unroll
        for (int j = 0; j < 4; j++) gv[1][j] = __ldg(gpc + j * j8);
    }
    {   // B chunk 0 -> buf0
        const __nv_bfloat16* w = g_wscr + w1base;
        uint32_t dst = smb + OFF_B;
#pragma unroll
        for (int i = tid; i < 2048; i += 256) {
            int pl = i >> 10, k = (i >> 5) & 31, cc = i & 31;
            cpa16(dst + pl * BPLANE + k * 528 + cc * 16, w + pl * Koff + k * 256 + cc * 8);
        }
    }
    CPA_COMMIT();

    for (int c = 0; c < nch; c++) {
        // 1. convert gather regs for chunk c -> A[c&1]
        {
            char* ab = sm + OFF_A + (c & 1) * ABUF;
#pragma unroll
            for (int j = 0; j < 4; j++) {
                float v = gv[c & 1][j];
                __nv_bfloat16 hi = __float2bfloat16(v);
                int o = grow * 80 + (ks + 8 * j) * 2;
                *(__nv_bfloat16*)(ab + o)        = hi;
                *(__nv_bfloat16*)(ab + 2560 + o) =
                    __float2bfloat16(v - __bfloat162float(hi));
            }
        }
        // 2. single barrier: A[c&1]/B[c&1] writes visible; prior readers done
        __syncthreads();
        // 3. issue gather for chunk c+2 (2-deep: ~2 chunk bodies of latency)
        if (c + 2 < nch) {
            const float* gpc = gp + (long long)(c + 2) * kb;
#pragma unroll
            for (int j = 0; j < 4; j++) gv[c & 1][j] = __ldg(gpc + j * j8);
        }
        // 4. stream B chunk c+1
        if (c + 1 < nch) {
            const __nv_bfloat16* w = g_wscr + w1base + (long long)(c + 1) * 8192;
            uint32_t dst = smb + OFF_B + ((c + 1) & 1) * BBUF;
#pragma unroll
            for (int i = tid; i < 2048; i += 256) {
                int pl = i >> 10, k = (i >> 5) & 31, cc = i & 31;
                cpa16(dst + pl * BPLANE + k * 528 + cc * 16, w + pl * Koff + k * 256 + cc * 8);
            }
            CPA_COMMIT();
            CPA_WAIT1();
        } else {
            CPA_WAIT0();
        }
        __syncwarp();
        // 5. MMA chunk c
        uint32_t aHi = aFr + (c & 1) * ABUF;
        uint32_t bb  = bFr + (c & 1) * BBUF;
#pragma unroll
        for (int kk = 0; kk < 2; kk++)
            mma_step(acc, aHi + kk * 32, aHi + 2560 + kk * 32, bb + kk * 16 * 528, wn);
    }

    // ---- stream GEMM2 B chunk0 into buf0 (safe: nch even; buf0 readers done) --
    const long long w2base = 917504LL + (long long)s * 131072;
    {
        const __nv_bfloat16* w = g_wscr + w2base;
        uint32_t dst = smb + OFF_B;
#pragma unroll
        for (int i = tid; i < 2048; i += 256) {
            int pl = i >> 10, k = (i >> 5) & 31, cc = i & 31;
            cpa16(dst + pl * BPLANE + k * 528 + cc * 16, w + pl * 65536 + k * 256 + cc * 8);
        }
    }
    CPA_COMMIT();

    // ---------------- epilogue 1: relu + bias -> hidden hi/lo ----------------
    {
        const float* __restrict__ b1 = p.b1[s];
        const int r0 = wm * 16 + g;
#pragma unroll
        for (int nf = 0; nf < 8; nf++) {
            int c0 = wn * 64 + nf * 8 + ti * 2;
            float ba = __ldg(b1 + c0), bbv = __ldg(b1 + c0 + 1);
            float v0 = fmaxf(acc[nf][0] + ba, 0.f);
            float v1 = fmaxf(acc[nf][1] + bbv, 0.f);
            float v2 = fmaxf(acc[nf][2] + ba, 0.f);
            float v3 = fmaxf(acc[nf][3] + bbv, 0.f);
            __nv_bfloat16 h0 = __float2bfloat16(v0), h1 = __float2bfloat16(v1);
            __nv_bfloat16 h2 = __float2bfloat16(v2), h3 = __float2bfloat16(v3);
            __nv_bfloat162 hi01; hi01.x = h0; hi01.y = h1;
            __nv_bfloat162 hi23; hi23.x = h2; hi23.y = h3;
            __nv_bfloat162 lo01, lo23;
            lo01.x = __float2bfloat16(v0 - __bfloat162float(h0));
            lo01.y = __float2bfloat16(v1 - __bfloat162float(h1));
            lo23.x = __float2bfloat16(v2 - __bfloat162float(h2));
            lo23.y = __float2bfloat16(v3 - __bfloat162float(h3));
            *(__nv_bfloat162*)(sm + OFF_H + r0 * 528 + c0 * 2)                = hi01;
            *(__nv_bfloat162*)(sm + OFF_H + (r0 + 8) * 528 + c0 * 2)          = hi23;
            *(__nv_bfloat162*)(sm + OFF_H + HPLANE + r0 * 528 + c0 * 2)       = lo01;
            *(__nv_bfloat162*)(sm + OFF_H + HPLANE + (r0 + 8) * 528 + c0 * 2) = lo23;
#pragma unroll
            for (int jj = 0; jj < 4; jj++) acc[nf][jj] = 0.f;
        }
    }

    // ---------------- GEMM2: K=256, 8 chunks ----------------
    const uint32_t aRow2 = smb + OFF_H + (wm * 16 + (lane & 15)) * 528 + (lane >> 4) * 16;
    for (int c2 = 0; c2 < 8; c2++) {
        __syncthreads();   // c2=0: hidden visible; c2>0: B buf reuse safe
        if (c2 + 1 < 8) {
            const __nv_bfloat16* w = g_wscr + w2base + (long long)(c2 + 1) * 8192;
            uint32_t dst = smb + OFF_B + ((c2 + 1) & 1) * BBUF;
#pragma unroll
            for (int i = tid; i < 2048; i += 256) {
                int pl = i >> 10, k = (i >> 5) & 31, cc = i & 31;
                cpa16(dst + pl * BPLANE + k * 528 + cc * 16, w + pl * 65536 + k * 256 + cc * 8);
            }
            CPA_COMMIT();
            CPA_WAIT1();
        } else {
            CPA_WAIT0();
        }
        __syncwarp();
        uint32_t bb = bFr + (c2 & 1) * BBUF;
#pragma unroll
        for (int kk = 0; kk < 2; kk++)
            mma_step(acc, aRow2 + c2 * 64 + kk * 32,
                     aRow2 + HPLANE + c2 * 64 + kk * 32, bb + kk * 16 * 528, wn);
    }

    // ---------------- epilogue 2: bias, L2 norm, store ----------------
    {
        const float* __restrict__ b2 = p.b2[s];
        float b2a[8], b2b[8];
#pragma unroll
        for (int nf = 0; nf < 8; nf++) {
            int c0 = wn * 64 + nf * 8 + ti * 2;
            b2a[nf] = __ldg(b2 + c0);
            b2b[nf] = __ldg(b2 + c0 + 1);
        }
        float s0 = 0.f, s1 = 0.f;
#pragma unroll
        for (int nf = 0; nf < 8; nf++) {
            float v0 = acc[nf][0] + b2a[nf], v1 = acc[nf][1] + b2b[nf];
            float v2 = acc[nf][2] + b2a[nf], v3 = acc[nf][3] + b2b[nf];
            s0 += v0 * v0 + v1 * v1;
            s1 += v2 * v2 + v3 * v3;
        }
        s0 += __shfl_xor_sync(0xffffffffu, s0, 1);
        s0 += __shfl_xor_sync(0xffffffffu, s0, 2);
        s1 += __shfl_xor_sync(0xffffffffu, s1, 1);
        s1 += __shfl_xor_sync(0xffffffffu, s1, 2);
        float* pn = (float*)(sm + OFF_PN);
        const int r0 = wm * 16 + g;
        if (ti == 0) {
            pn[wn * 32 + r0]     = s0;
            pn[wn * 32 + r0 + 8] = s1;
        }
        __syncthreads();
        float t0 = pn[r0] + pn[32 + r0] + pn[64 + r0] + pn[96 + r0];
        float t1 = pn[r0 + 8] + pn[32 + r0 + 8] + pn[64 + r0 + 8] + pn[96 + r0 + 8];
        float sc0 = 1.f / (sqrtf(t0) + 1e-7f);
        float sc1 = 1.f / (sqrtf(t1) + 1e-7f);
        float* o0 = p.out + ((long long)s * 4096 + m0 + r0) * 256;
        float* o1 = o0 + 8 * 256;
#pragma unroll
        for (int nf = 0; nf < 8; nf++) {
            int c0 = wn * 64 + nf * 8 + ti * 2;
            float2 u0, u1;
            u0.x = (acc[nf][0] + b2a[nf]) * sc0;
            u0.y = (acc[nf][1] + b2b[nf]) * sc0;
            u1.x = (acc[nf][2] + b2a[nf]) * sc1;
            u1.y = (acc[nf][3] + b2b[nf]) * sc1;
            *(float2*)(o0 + c0) = u0;
            *(float2*)(o1 + c0) = u1;
        }
    }
}

// ==========================================================================
extern "C" void kernel_launch(void* const* d_in, const int* in_sizes, int n_in,
                              void* d_out, int out_size) {
    (void)n_in; (void)out_size;
    int fi[3], pi[3], w1i[3], b1i[3], w2i[3], b2i[3];
    if (in_sizes[1] == 256) {
        for (int s = 0; s < 3; s++) {  // dict order: feat,pid,w1,b1,w2,b2 per stage
            int b = 6 * s;
            fi[s] = b; pi[s] = b + 1; w1i[s] = b + 2;
            b1i[s] = b + 3; w2i[s] = b + 4; b2i[s] = b + 5;
        }
    } else {
        for (int s = 0; s < 3; s++) {  // signature order
            fi[s] = s; pi[s] = 3 + s;
            int b = 6 + 4 * s;
            w1i[s] = b; b1i[s] = b + 1; w2i[s] = b + 2; b2i[s] = b + 3;
        }
    }

    PrepP pw;
    MP p;
    for (int s = 0; s < 3; s++) {
        p.feat[s] = (const float*)d_in[fi[s]];
        p.pid[s]  = (const void*)d_in[pi[s]];
        pw.w1[s]  = (const float*)d_in[w1i[s]];
        p.b1[s]   = (const float*)d_in[b1i[s]];
        pw.w2[s]  = (const float*)d_in[w2i[s]];
        p.b2[s]   = (const float*)d_in[b2i[s]];
        p.C[s]    = in_sizes[w1i[s]] / 256;
        p.HW[s]   = in_sizes[fi[s]] / (16 * p.C[s]);
    }
    p.out = (float*)d_out;

    static bool attr_set = false;
    if (!attr_set) {
        cudaFuncSetAttribute(patch_mlp_mma,
                             cudaFuncAttributeMaxDynamicSharedMemorySize,
                             SMEM_ALLOC);
        attr_set = true;
    }

    prep_weights<<<640, 256>>>(pw);
    patch_mlp_mma<<<384, 256, SMEM_ALLOC>>>(p);
}

// round 9
// speedup vs baseline: 1.6156x; 1.2323x over previous
#include <cuda_runtime.h>
#include <cuda_bf16.h>
#include <cstdint>

// ==========================================================================
// Scratch:
//  g_wscr: pre-split bf16 hi/lo weights, row-major [K][256] per plane.
//    w1 stage bases {0, 131072, 393216} (elements), lo plane at +K*256.
//    w2 stage s: 917504 + s*131072, lo at +65536.
//  g_xscr: gathered A-chunk records, 4096B each:
//    [hi plane 32 rows x 64B][lo plane 32 rows x 64B], row = tile-local m,
//    64B = 32 k x bf16. Stage bases (bytes): {0, 4194304, 12582912}.
//    record(s, tile, ch) = base_s + (tile*nch_s + ch)*4096.
// ==========================================================================
__device__ __align__(16) __nv_bfloat16 g_wscr[1310720];
__device__ __align__(16) char g_xscr[29360128];

// ---------------- PTX helpers (baseline sm_80+ PTX only) ----------------
__device__ __forceinline__ uint32_t s2u(const void* p) {
    return (uint32_t)__cvta_generic_to_shared(p);
}
__device__ __forceinline__ void ldsm4(uint32_t* r, uint32_t a) {
    asm volatile("ldmatrix.sync.aligned.m8n8.x4.shared.b16 {%0,%1,%2,%3}, [%4];"
                 : "=r"(r[0]), "=r"(r[1]), "=r"(r[2]), "=r"(r[3]) : "r"(a));
}
__device__ __forceinline__ void ldsm4t(uint32_t* r, uint32_t a) {
    asm volatile("ldmatrix.sync.aligned.m8n8.x4.trans.shared.b16 {%0,%1,%2,%3}, [%4];"
                 : "=r"(r[0]), "=r"(r[1]), "=r"(r[2]), "=r"(r[3]) : "r"(a));
}
__device__ __forceinline__ void mma_bf16(float* d, const uint32_t* a,
                                         uint32_t b0, uint32_t b1) {
    asm volatile(
        "mma.sync.aligned.m16n8k16.row.col.f32.bf16.bf16.f32 "
        "{%0,%1,%2,%3}, {%4,%5,%6,%7}, {%8,%9}, {%0,%1,%2,%3};"
        : "+f"(d[0]), "+f"(d[1]), "+f"(d[2]), "+f"(d[3])
        : "r"(a[0]), "r"(a[1]), "r"(a[2]), "r"(a[3]), "r"(b0), "r"(b1));
}
__device__ __forceinline__ void cpa16(uint32_t dst, const void* src) {
    asm volatile("cp.async.cg.shared.global [%0], [%1], 16;" :: "r"(dst), "l"(src));
}
#define CPA_COMMIT() asm volatile("cp.async.commit_group;" ::: "memory")
#define CPA_WAIT1()  asm volatile("cp.async.wait_group 1;" ::: "memory")
#define CPA_WAIT0()  asm volatile("cp.async.wait_group 0;" ::: "memory")

// ==========================================================================
// Kernel 1: gather (blocks 0..383) + weight prep (blocks 384..447).
// Gather: block = (stage, tile of 32 rows). lane <-> tile row (patch);
// warp w handles chunks w, w+8, ... For each chunk: 32 strided channel
// loads per lane (lane addresses share lines within the HW window ->
// L1tex merging), convert to bf16 hi/lo, coalesced 64B-row stores.
// ==========================================================================
struct GP {
    const float* feat[3];
    const void*  pid[3];
    const float* w1[3];
    const float* w2[3];
    int C[3];
    int HW[3];
};

__global__ __launch_bounds__(256, 3) void gather_prep(GP g) {
    const int bid = blockIdx.x;
    const int tid = threadIdx.x;

    if (bid >= 384) {  // ---- weight prep ----
        for (int idx = (bid - 384) * 256 + tid; idx < 655360; idx += 64 * 256) {
            int s, j;
            const float* src;
            long long hioff, looff;
            if (idx < 458752) {
                if (idx < 65536)       { s = 0; j = idx;          hioff = 0;      looff = 65536; }
                else if (idx < 196608) { s = 1; j = idx - 65536;  hioff = 131072; looff = 262144; }
                else                   { s = 2; j = idx - 196608; hioff = 393216; looff = 655360; }
                src = g.w1[s];
            } else {
                int i = idx - 458752;
                s = i >> 16; j = i & 65535;
                src = g.w2[s];
                hioff = 917504LL + s * 131072;
                looff = hioff + 65536;
            }
            float v = src[j];
            __nv_bfloat16 hi = __float2bfloat16(v);
            __nv_bfloat16 lo = __float2bfloat16(v - __bfloat162float(hi));
            g_wscr[hioff + j] = hi;
            g_wscr[looff + j] = lo;
        }
        return;
    }

    // ---- gather ----
    __shared__ int flag;
    const int s    = bid % 3;
    const int tile = bid / 3;
    const int C    = g.C[s];
    const long long HW = g.HW[s];

    if (tid == 0) flag = 1;
    __syncthreads();
    if (tid < 128) {
        long long v = ((const long long*)g.pid[s])[tid];
        if (v < 0 || v >= HW) flag = 0;
    }
    __syncthreads();
    const int is64 = flag;

    const int lane = tid & 31, w = tid >> 5;
    const int m = tile * 32 + lane, b = m >> 8, pp = m & 255;
    long long sp = is64 ? ((const long long*)g.pid[s])[pp]
                        : (long long)((const int*)g.pid[s])[pp];
    const float* base = g.feat[s] + (long long)b * C * HW + sp;
    const int nch = C >> 5;
    const long long xb = (s == 0) ? 0LL : (s == 1) ? 4194304LL : 12582912LL;

    for (int ch = w; ch < nch; ch += 8) {
        const float* fp = base + (long long)(ch << 5) * HW;
        float v[32];
#pragma unroll
        for (int kk = 0; kk < 32; kk++) v[kk] = __ldg(fp + (long long)kk * HW);
        char* rec = g_xscr + xb + (long long)(tile * nch + ch) * 4096 + lane * 64;
#pragma unroll
        for (int q = 0; q < 4; q++) {
            uint32_t hw_[4], lw_[4];
#pragma unroll
            for (int j = 0; j < 4; j++) {
                float a = v[q * 8 + j * 2], c2 = v[q * 8 + j * 2 + 1];
                __nv_bfloat16 ha = __float2bfloat16(a), hc = __float2bfloat16(c2);
                __nv_bfloat16 la = __float2bfloat16(a - __bfloat162float(ha));
                __nv_bfloat16 lc = __float2bfloat16(c2 - __bfloat162float(hc));
                hw_[j] = (uint32_t)(*(uint16_t*)&ha) | ((uint32_t)(*(uint16_t*)&hc) << 16);
                lw_[j] = (uint32_t)(*(uint16_t*)&la) | ((uint32_t)(*(uint16_t*)&lc) << 16);
            }
            *(uint4*)(rec + q * 16)        = make_uint4(hw_[0], hw_[1], hw_[2], hw_[3]);
            *(uint4*)(rec + 2048 + q * 16) = make_uint4(lw_[0], lw_[1], lw_[2], lw_[3]);
        }
    }
}

// ==========================================================================
// Kernel 2: GEMM. MT=32 rows/block, KC=32, 256 thr = 8 warps (2M x 4N).
// A and B both arrive via coalesced cp.async; no divergent loads.
// ==========================================================================
struct MP {
    const float* b1[3];
    const float* b2[3];
    float* out;
    int C[3];
};

// smem (A rows 80B padded; B/hidden rows 528B padded)
constexpr int ABUF    = 5120;         // hi(2560)+lo(2560) per buffer
constexpr int OFF_A   = 0;            // 2 buffers
constexpr int OFF_B   = 10240;        // 2 bufs x (hi+lo) x 32 x 528
constexpr int BPLANE  = 16896;
constexpr int BBUF    = 33792;
constexpr int OFF_H   = 77824;        // hidden hi/lo planes
constexpr int HPLANE  = 16896;
constexpr int OFF_PN  = 111616;       // float pn[4][32]
constexpr int SMEM_ALLOC = 112128;

// One K16 x 128-col step for this warp (both A splits vs hi/lo B).
__device__ __forceinline__ void mma_step(float acc[8][4], uint32_t aHi,
                                         uint32_t aLo, uint32_t bRow, int wn) {
    uint32_t ah[4], al[4];
    ldsm4(ah, aHi);
    ldsm4(al, aLo);
#pragma unroll
    for (int pr = 0; pr < 4; pr++) {
        uint32_t bh[4], bl[4];
        uint32_t bc = bRow + (uint32_t)(wn * 64 + pr * 16) * 2;
        ldsm4t(bh, bc);
        ldsm4t(bl, bc + BPLANE);
        mma_bf16(acc[pr * 2], ah, bh[0], bh[1]);
        mma_bf16(acc[pr * 2], ah, bl[0], bl[1]);
        mma_bf16(acc[pr * 2], al, bh[0], bh[1]);
        mma_bf16(acc[pr * 2 + 1], ah, bh[2], bh[3]);
        mma_bf16(acc[pr * 2 + 1], ah, bl[2], bl[3]);
        mma_bf16(acc[pr * 2 + 1], al, bh[2], bh[3]);
    }
}

// Issue one GEMM1 chunk: A record (256 cpa16) + B chunk (2048 cpa16).
__device__ __forceinline__ void issue_chunk1(uint32_t smb, int buf,
                                             const char* arec,
                                             const __nv_bfloat16* wsrc,
                                             long long Koff, int tid) {
    const uint32_t adst = smb + OFF_A + buf * ABUF;
    const uint32_t bdst = smb + OFF_B + buf * BBUF;
#pragma unroll
    for (int r = 0; r < 9; r++) {
        int i = r * 256 + tid;
        if (i < 256) {
            int pl = i >> 7, rw = (i >> 2) & 31, q = i & 3;
            cpa16(adst + pl * 2560 + rw * 80 + q * 16, arec + i * 16);
        } else {
            int j = i - 256;
            int pl = j >> 10, k = (j >> 5) & 31, cc = j & 31;
            cpa16(bdst + pl * BPLANE + k * 528 + cc * 16,
                  wsrc + pl * Koff + k * 256 + cc * 8);
        }
    }
}

__device__ __forceinline__ void issue_chunk2(uint32_t smb, int buf,
                                             const __nv_bfloat16* wsrc, int tid) {
    const uint32_t bdst = smb + OFF_B + buf * BBUF;
#pragma unroll
    for (int r = 0; r < 8; r++) {
        int j = r * 256 + tid;
        int pl = j >> 10, k = (j >> 5) & 31, cc = j & 31;
        cpa16(bdst + pl * BPLANE + k * 528 + cc * 16,
              wsrc + pl * 65536 + k * 256 + cc * 8);
    }
}

__global__ __launch_bounds__(256, 2) void patch_mlp_mma(MP p) {
    extern __shared__ char sm[];
    const int tid  = threadIdx.x;
    const int lane = tid & 31;
    const int wid  = tid >> 5;
    const int wm   = wid & 1;        // M group (16 rows)
    const int wn   = wid >> 1;       // N group (64 cols), 0..3
    const int ti   = lane & 3;
    const int g    = lane >> 2;

    const int s    = blockIdx.x % 3;
    const int tile = blockIdx.x / 3;
    const int m0   = tile * 32;
    const int C    = p.C[s];
    const int nch  = C >> 5;

    const long long xb     = (s == 0) ? 0LL : (s == 1) ? 4194304LL : 12582912LL;
    const char*     xrec   = g_xscr + xb + (long long)tile * nch * 4096;
    const long long w1base = (s == 0) ? 0LL : (s == 1) ? 131072LL : 393216LL;
    const long long Koff   = (long long)C * 256;

    const uint32_t smb = s2u(sm);
    const uint32_t aFr = smb + OFF_A + (wm * 16 + (lane & 15)) * 80 + (lane >> 4) * 16;
    const uint32_t bFr = smb + OFF_B + (lane & 15) * 528 + (lane >> 4) * 16;

    float acc[8][4];
#pragma unroll
    for (int i = 0; i < 8; i++)
#pragma unroll
        for (int jj = 0; jj < 4; jj++) acc[i][jj] = 0.f;

    // ---------------- GEMM1 ----------------
    issue_chunk1(smb, 0, xrec, g_wscr + w1base, Koff, tid);
    CPA_COMMIT();

    for (int c = 0; c < nch; c++) {
        if (c + 1 < nch) {
            issue_chunk1(smb, (c + 1) & 1, xrec + (long long)(c + 1) * 4096,
                         g_wscr + w1base + (long long)(c + 1) * 8192, Koff, tid);
            CPA_COMMIT();
            CPA_WAIT1();     // own group(c) landed
        } else {
            CPA_WAIT0();
        }
        __syncthreads();     // all threads' group(c) data visible
        uint32_t aHi = aFr + (c & 1) * ABUF;
        uint32_t bb  = bFr + (c & 1) * BBUF;
#pragma unroll
        for (int kk = 0; kk < 2; kk++)
            mma_step(acc, aHi + kk * 32, aHi + 2560 + kk * 32, bb + kk * 16 * 528, wn);
        __syncthreads();     // everyone done reading buf (c&1) before reuse
    }

    // ---- GEMM2 chunk0 -> buf0 (nch even: buf0's last readers are done) ----
    const long long w2base = 917504LL + (long long)s * 131072;
    issue_chunk2(smb, 0, g_wscr + w2base, tid);
    CPA_COMMIT();

    // ---------------- epilogue 1: relu + bias -> hidden hi/lo ----------------
    {
        const float* __restrict__ b1 = p.b1[s];
        const int r0 = wm * 16 + g;
#pragma unroll
        for (int nf = 0; nf < 8; nf++) {
            int c0 = wn * 64 + nf * 8 + ti * 2;
            float ba = __ldg(b1 + c0), bbv = __ldg(b1 + c0 + 1);
            float v0 = fmaxf(acc[nf][0] + ba, 0.f);
            float v1 = fmaxf(acc[nf][1] + bbv, 0.f);
            float v2 = fmaxf(acc[nf][2] + ba, 0.f);
            float v3 = fmaxf(acc[nf][3] + bbv, 0.f);
            __nv_bfloat16 h0 = __float2bfloat16(v0), h1 = __float2bfloat16(v1);
            __nv_bfloat16 h2 = __float2bfloat16(v2), h3 = __float2bfloat16(v3);
            __nv_bfloat162 hi01; hi01.x = h0; hi01.y = h1;
            __nv_bfloat162 hi23; hi23.x = h2; hi23.y = h3;
            __nv_bfloat162 lo01, lo23;
            lo01.x = __float2bfloat16(v0 - __bfloat162float(h0));
            lo01.y = __float2bfloat16(v1 - __bfloat162float(h1));
            lo23.x = __float2bfloat16(v2 - __bfloat162float(h2));
            lo23.y = __float2bfloat16(v3 - __bfloat162float(h3));
            *(__nv_bfloat162*)(sm + OFF_H + r0 * 528 + c0 * 2)                = hi01;
            *(__nv_bfloat162*)(sm + OFF_H + (r0 + 8) * 528 + c0 * 2)          = hi23;
            *(__nv_bfloat162*)(sm + OFF_H + HPLANE + r0 * 528 + c0 * 2)       = lo01;
            *(__nv_bfloat162*)(sm + OFF_H + HPLANE + (r0 + 8) * 528 + c0 * 2) = lo23;
#pragma unroll
            for (int jj = 0; jj < 4; jj++) acc[nf][jj] = 0.f;
        }
    }

    // ---------------- GEMM2: K=256, 8 chunks ----------------
    const uint32_t aRow2 = smb + OFF_H + (wm * 16 + (lane & 15)) * 528 + (lane >> 4) * 16;
    for (int c2 = 0; c2 < 8; c2++) {
        if (c2 + 1 < 8) {
            issue_chunk2(smb, (c2 + 1) & 1,
                         g_wscr + w2base + (long long)(c2 + 1) * 8192, tid);
            CPA_COMMIT();
            CPA_WAIT1();
        } else {
            CPA_WAIT0();
        }
        __syncthreads();     // H + group(c2) visible
        uint32_t bb = bFr + (c2 & 1) * BBUF;
#pragma unroll
        for (int kk = 0; kk < 2; kk++)
            mma_step(acc, aRow2 + c2 * 64 + kk * 32,
                     aRow2 + HPLANE + c2 * 64 + kk * 32, bb + kk * 16 * 528, wn);
        __syncthreads();
    }

    // ---------------- epilogue 2: bias, L2 norm, store ----------------
    {
        const float* __restrict__ b2 = p.b2[s];
        float b2a[8], b2b[8];
#pragma unroll
        for (int nf = 0; nf < 8; nf++) {
            int c0 = wn * 64 + nf * 8 + ti * 2;
            b2a[nf] = __ldg(b2 + c0);
            b2b[nf] = __ldg(b2 + c0 + 1);
        }
        float s0 = 0.f, s1 = 0.f;
#pragma unroll
        for (int nf = 0; nf < 8; nf++) {
            float v0 = acc[nf][0] + b2a[nf], v1 = acc[nf][1] + b2b[nf];
            float v2 = acc[nf][2] + b2a[nf], v3 = acc[nf][3] + b2b[nf];
            s0 += v0 * v0 + v1 * v1;
            s1 += v2 * v2 + v3 * v3;
        }
        s0 += __shfl_xor_sync(0xffffffffu, s0, 1);
        s0 += __shfl_xor_sync(0xffffffffu, s0, 2);
        s1 += __shfl_xor_sync(0xffffffffu, s1, 1);
        s1 += __shfl_xor_sync(0xffffffffu, s1, 2);
        float* pn = (float*)(sm + OFF_PN);
        const int r0 = wm * 16 + g;
        if (ti == 0) {
            pn[wn * 32 + r0]     = s0;
            pn[wn * 32 + r0 + 8] = s1;
        }
        __syncthreads();
        float t0 = pn[r0] + pn[32 + r0] + pn[64 + r0] + pn[96 + r0];
        float t1 = pn[r0 + 8] + pn[32 + r0 + 8] + pn[64 + r0 + 8] + pn[96 + r0 + 8];
        float sc0 = 1.f / (sqrtf(t0) + 1e-7f);
        float sc1 = 1.f / (sqrtf(t1) + 1e-7f);
        float* o0 = p.out + ((long long)s * 4096 + m0 + r0) * 256;
        float* o1 = o0 + 8 * 256;
#pragma unroll
        for (int nf = 0; nf < 8; nf++) {
            int c0 = wn * 64 + nf * 8 + ti * 2;
            float2 u0, u1;
            u0.x = (acc[nf][0] + b2a[nf]) * sc0;
            u0.y = (acc[nf][1] + b2b[nf]) * sc0;
            u1.x = (acc[nf][2] + b2a[nf]) * sc1;
            u1.y = (acc[nf][3] + b2b[nf]) * sc1;
            *(float2*)(o0 + c0) = u0;
            *(float2*)(o1 + c0) = u1;
        }
    }
}

// ==========================================================================
extern "C" void kernel_launch(void* const* d_in, const int* in_sizes, int n_in,
                              void* d_out, int out_size) {
    (void)n_in; (void)out_size;
    int fi[3], pi[3], w1i[3], b1i[3], w2i[3], b2i[3];
    if (in_sizes[1] == 256) {
        for (int s = 0; s < 3; s++) {  // dict order: feat,pid,w1,b1,w2,b2 per stage
            int b = 6 * s;
            fi[s] = b; pi[s] = b + 1; w1i[s] = b + 2;
            b1i[s] = b + 3; w2i[s] = b + 4; b2i[s] = b + 5;
        }
    } else {
        for (int s = 0; s < 3; s++) {  // signature order
            fi[s] = s; pi[s] = 3 + s;
            int b = 6 + 4 * s;
            w1i[s] = b; b1i[s] = b + 1; w2i[s] = b + 2; b2i[s] = b + 3;
        }
    }

    GP gp;
    MP p;
    for (int s = 0; s < 3; s++) {
        gp.feat[s] = (const float*)d_in[fi[s]];
        gp.pid[s]  = (const void*)d_in[pi[s]];
        gp.w1[s]   = (const float*)d_in[w1i[s]];
        gp.w2[s]   = (const float*)d_in[w2i[s]];
        p.b1[s]    = (const float*)d_in[b1i[s]];
        p.b2[s]    = (const float*)d_in[b2i[s]];
        gp.C[s]    = in_sizes[w1i[s]] / 256;
        p.C[s]     = gp.C[s];
        gp.HW[s]   = in_sizes[fi[s]] / (16 * gp.C[s]);
    }
    p.out = (float*)d_out;

    static bool attr_set = false;
    if (!attr_set) {
        cudaFuncSetAttribute(patch_mlp_mma,
                             cudaFuncAttributeMaxDynamicSharedMemorySize,
                             SMEM_ALLOC);
        attr_set = true;
    }

    gather_prep<<<448, 256>>>(gp);
    patch_mlp_mma<<<384, 256, SMEM_ALLOC>>>(p);
}